// round 1
// baseline (speedup 1.0000x reference)
#include <cuda_runtime.h>

#define SEQ   2048
#define HIDN  2048
#define NH    16
#define HD    128
#define NBLK  32
#define BLK   64
#define KSEL  8

// ---- scratch (device globals: no allocation allowed) ----
__device__ float    g_q[SEQ * HIDN];
__device__ float    g_k[SEQ * HIDN];
__device__ float    g_v[SEQ * HIDN];
__device__ float    g_kg[NBLK * HIDN];
__device__ unsigned g_sel[NH * SEQ];
__device__ float    g_o[SEQ * HIDN];

__device__ __forceinline__ float finf() { return __int_as_float(0x7f800000); }

// ============================================================
// SGEMM: C[2048x2048] = A[2048x2048] @ B[2048x2048], row-major.
// 128x128 tile, BK=8, 256 threads, 8x8 microtile.
// ============================================================
__device__ __forceinline__ void sgemm_body(const float* __restrict__ A,
                                           const float* __restrict__ B,
                                           float* __restrict__ C) {
    __shared__ float As[8 * 128];   // [k][m] (transposed)
    __shared__ float Bs[8 * 128];   // [k][n]

    const int tid  = threadIdx.x;
    const int cRow = blockIdx.y * 128;
    const int cCol = blockIdx.x * 128;
    const int tRow = (tid >> 4) * 8;      // 0..120
    const int tCol = (tid & 15) * 8;      // 0..120
    const int aRow = tid >> 1;            // 0..127
    const int aCol = (tid & 1) << 2;      // 0 or 4
    const int bRow = tid >> 5;            // 0..7
    const int bCol = (tid & 31) << 2;     // 0..124

    float acc[8][8];
#pragma unroll
    for (int i = 0; i < 8; i++)
#pragma unroll
        for (int j = 0; j < 8; j++) acc[i][j] = 0.f;

    float rM[8], rN[8];

    for (int k0 = 0; k0 < HIDN; k0 += 8) {
        float4 a4 = *(const float4*)(A + (size_t)(cRow + aRow) * HIDN + k0 + aCol);
        As[(aCol + 0) * 128 + aRow] = a4.x;
        As[(aCol + 1) * 128 + aRow] = a4.y;
        As[(aCol + 2) * 128 + aRow] = a4.z;
        As[(aCol + 3) * 128 + aRow] = a4.w;
        *(float4*)(Bs + bRow * 128 + bCol) =
            *(const float4*)(B + (size_t)(k0 + bRow) * HIDN + cCol + bCol);
        __syncthreads();
#pragma unroll
        for (int kk = 0; kk < 8; kk++) {
#pragma unroll
            for (int i = 0; i < 8; i++) rM[i] = As[kk * 128 + tRow + i];
#pragma unroll
            for (int j = 0; j < 8; j++) rN[j] = Bs[kk * 128 + tCol + j];
#pragma unroll
            for (int i = 0; i < 8; i++)
#pragma unroll
                for (int j = 0; j < 8; j++) acc[i][j] += rM[i] * rN[j];
        }
        __syncthreads();
    }

    float* Cp = C + (size_t)cRow * HIDN + cCol;
#pragma unroll
    for (int i = 0; i < 8; i++)
#pragma unroll
        for (int j = 0; j < 8; j += 4) {
            float4 c4 = make_float4(acc[i][j], acc[i][j + 1], acc[i][j + 2], acc[i][j + 3]);
            *(float4*)(Cp + (size_t)(tRow + i) * HIDN + tCol + j) = c4;
        }
}

// QKV fused: blockIdx.z selects which projection.
__global__ __launch_bounds__(256, 2) void sgemm_qkv_kernel(const float* __restrict__ hs,
                                                           const float* __restrict__ Wq,
                                                           const float* __restrict__ Wk,
                                                           const float* __restrict__ Wv) {
    const float* W;
    float* C;
    if (blockIdx.z == 0)      { W = Wq; C = g_q; }
    else if (blockIdx.z == 1) { W = Wk; C = g_k; }
    else                      { W = Wv; C = g_v; }
    sgemm_body(hs, W, C);
}

__global__ __launch_bounds__(256, 2) void sgemm_out_kernel(const float* __restrict__ Wo,
                                                           float* __restrict__ out) {
    sgemm_body(g_o, Wo, out);
}

// ============================================================
// kg[n][c] = mean over 64 rows of k
// ============================================================
__global__ void kgmean_kernel() {
    const int n = blockIdx.x;
    for (int c = threadIdx.x; c < HIDN; c += blockDim.x) {
        float sum = 0.f;
#pragma unroll
        for (int t = 0; t < BLK; t++)
            sum += g_k[(size_t)(n * BLK + t) * HIDN + c];
        g_kg[n * HIDN + c] = sum * (1.0f / 64.0f);
    }
}

// ============================================================
// Gate + top-8 selection. Block = (h, 32 query rows), 8 warps,
// each warp handles 4 rows; lane = candidate block index (nb==32).
// Selected set stored as 32-bit mask; -inf picks (future blocks) dropped.
// ============================================================
__global__ __launch_bounds__(256) void gate_topk_kernel() {
    __shared__ float kgs[NBLK * 129];
    const int h  = blockIdx.y;
    const int s0 = blockIdx.x * 32;
    const int tid = threadIdx.x;

    for (int i = tid; i < NBLK * HD; i += 256) {
        int n = i >> 7, d = i & 127;
        kgs[n * 129 + d] = g_kg[n * HIDN + h * HD + d];
    }
    __syncthreads();

    const int warp = tid >> 5, lane = tid & 31;
    for (int r = 0; r < 4; r++) {
        const int s = s0 + warp * 4 + r;
        const float* qrow = g_q + (size_t)s * HIDN + h * HD;
        float g = 0.f;
#pragma unroll 8
        for (int d = 0; d < HD; d++)
            g += __ldg(qrow + d) * kgs[lane * 129 + d];

        const int qb = s >> 6;
        if (lane == qb)      g =  finf();
        else if (lane > qb)  g = -finf();

        unsigned mask = 0;
        float work = g;
#pragma unroll
        for (int it = 0; it < KSEL; it++) {
            float v = work; int idx = lane;
#pragma unroll
            for (int off = 16; off; off >>= 1) {
                float ov = __shfl_xor_sync(0xffffffffu, v, off);
                int   oi = __shfl_xor_sync(0xffffffffu, idx, off);
                if (ov > v || (ov == v && oi < idx)) { v = ov; idx = oi; }
            }
            if (v > -finf()) mask |= (1u << idx);
            if (lane == idx) work = -finf();
        }
        if (lane == 0) g_sel[h * SEQ + s] = mask;
    }
}

// ============================================================
// Block-sparse causal attention, one CTA (128 threads) per (h, s).
// Online softmax across selected key blocks; k/v tiles in smem with
// stride-129 padding for conflict-free access.
// ============================================================
__global__ __launch_bounds__(128) void attn_kernel() {
    __shared__ float kb[BLK * 129];
    __shared__ float qs[HD];
    __shared__ float sc[BLK];
    __shared__ float red[2];

    const int h   = blockIdx.x >> 11;
    const int s   = blockIdx.x & (SEQ - 1);
    const int tid = threadIdx.x;

    qs[tid] = g_q[(size_t)s * HIDN + h * HD + tid];
    unsigned mask = g_sel[h * SEQ + s];
    const float sm_scale = 0.08838834764831845f;  // 1/sqrt(128)

    float m = -finf(), l = 0.f, acc = 0.f;
    __syncthreads();

    while (mask) {
        const int n = __ffs(mask) - 1;
        mask &= mask - 1;

        // load K block (coalesced rows, transposed-ish via padded stride)
        const float* kbase = g_k + (size_t)(n * BLK) * HIDN + h * HD + tid;
#pragma unroll 8
        for (int t = 0; t < BLK; t++)
            kb[t * 129 + tid] = kbase[(size_t)t * HIDN];
        __syncthreads();

        // scores
        if (tid < BLK) {
            const int kp = n * BLK + tid;
            if (kp <= s) {
                float d0 = 0.f;
#pragma unroll 8
                for (int d = 0; d < HD; d++)
                    d0 += qs[d] * kb[tid * 129 + d];
                sc[tid] = d0 * sm_scale;
            } else {
                sc[tid] = -finf();
            }
        }
        __syncthreads();

        // block max
        if (tid < 32) {
            float a = fmaxf(sc[tid], sc[tid + 32]);
#pragma unroll
            for (int off = 16; off; off >>= 1)
                a = fmaxf(a, __shfl_xor_sync(0xffffffffu, a, off));
            if (tid == 0) red[0] = a;
        }
        __syncthreads();

        const float newm  = fmaxf(m, red[0]);       // finite: every selected block has a causal key
        const float alpha = expf(m - newm);          // m=-inf -> 0
        if (tid < BLK) sc[tid] = expf(sc[tid] - newm);
        __syncthreads();

        // block sum of p
        if (tid < 32) {
            float a = sc[tid] + sc[tid + 32];
#pragma unroll
            for (int off = 16; off; off >>= 1)
                a += __shfl_xor_sync(0xffffffffu, a, off);
            if (tid == 0) red[1] = a;
        }
        __syncthreads();

        l = l * alpha + red[1];
        m = newm;

        // load V block into same buffer
        const float* vbase = g_v + (size_t)(n * BLK) * HIDN + h * HD + tid;
#pragma unroll 8
        for (int t = 0; t < BLK; t++)
            kb[t * 129 + tid] = vbase[(size_t)t * HIDN];
        __syncthreads();

        acc *= alpha;
#pragma unroll 16
        for (int t = 0; t < BLK; t++)
            acc += sc[t] * kb[t * 129 + tid];
        __syncthreads();   // protect kb/sc before next iteration
    }

    g_o[(size_t)s * HIDN + h * HD + tid] = acc / l;
}

// ============================================================
extern "C" void kernel_launch(void* const* d_in, const int* in_sizes, int n_in,
                              void* d_out, int out_size) {
    const float* hs = (const float*)d_in[0];
    const float* Wq = (const float*)d_in[1];
    const float* Wk = (const float*)d_in[2];
    const float* Wv = (const float*)d_in[3];
    const float* Wo = (const float*)d_in[4];
    float* out = (float*)d_out;

    dim3 gq(HIDN / 128, SEQ / 128, 3);
    sgemm_qkv_kernel<<<gq, 256>>>(hs, Wq, Wk, Wv);

    kgmean_kernel<<<NBLK, 256>>>();

    dim3 gg(SEQ / 32, NH);
    gate_topk_kernel<<<gg, 256>>>();

    attn_kernel<<<NH * SEQ, 128>>>();

    dim3 go(HIDN / 128, SEQ / 128);
    sgemm_out_kernel<<<go, 256>>>(Wo, out);
}